// round 16
// baseline (speedup 1.0000x reference)
#include <cuda_runtime.h>
#include <math.h>

#define TWO_PI_F 6.283185307179586f
#define L2E_F    1.4426950408889634f

typedef unsigned long long ull;

// ---------------------------------------------------------------------------
// Scratch (single __device__ array)
// ---------------------------------------------------------------------------
constexpr int NBUF = 163840;   // max pairs*N = 128*1280 (layer1)
constexpr int NA   = 2048;     // max B*Co*K

__device__ float g_scratch[(size_t)22*NBUF + 6*NA + 512];

__device__ __forceinline__ float* gW()        { return g_scratch + 0*(size_t)NBUF; }
__device__ __forceinline__ float* gP0()       { return g_scratch + 1*(size_t)NBUF; }
__device__ __forceinline__ float* gP1()       { return g_scratch + 2*(size_t)NBUF; }
__device__ __forceinline__ float* gC00()      { return g_scratch + 3*(size_t)NBUF; }
__device__ __forceinline__ float* gC01()      { return g_scratch + 4*(size_t)NBUF; }
__device__ __forceinline__ float* gC11()      { return g_scratch + 5*(size_t)NBUF; }
__device__ __forceinline__ float* gAcc(int c) { return g_scratch + (size_t)(6+c)*NBUF; }
__device__ __forceinline__ float* gA(int k)   { return g_scratch + 22*(size_t)NBUF + (size_t)k*NA; }
__device__ __forceinline__ float* gX()        { return g_scratch + 22*(size_t)NBUF + 6*(size_t)NA; }
__device__ __forceinline__ float* gY()        { return gX() + 96; }   // [10][8][3] partials

__device__ __forceinline__ float ex2f(float x){
    float r; asm("ex2.approx.ftz.f32 %0, %1;" : "=f"(r) : "f"(x)); return r;
}
__device__ __forceinline__ ull pk2(float lo, float hi){
    ull r; asm("mov.b64 %0, {%1, %2};" : "=l"(r) : "f"(lo), "f"(hi)); return r;
}
__device__ __forceinline__ void upk2(float& lo, float& hi, ull v){
    asm("mov.b64 {%0, %1}, %2;" : "=f"(lo), "=f"(hi) : "l"(v));
}
__device__ __forceinline__ ull ffma2(ull a, ull b, ull c){
    ull d; asm("fma.rn.f32x2 %0, %1, %2, %3;" : "=l"(d) : "l"(a), "l"(b), "l"(c)); return d;
}
__device__ __forceinline__ ull umax64(ull a, ull b){ return a > b ? a : b; }
__device__ __forceinline__ unsigned redux_max(unsigned v){
    unsigned r; asm("redux.sync.max.u32 %0, %1, 0xffffffff;" : "=r"(r) : "r"(v)); return r;
}

// ---------------------------------------------------------------------------
// norm0: per-sample CovScaleNorm + WeightNorm on input GM (L=1, N=128)
// ---------------------------------------------------------------------------
__global__ void norm0_kernel(const float* __restrict__ in_w,
                             const float* __restrict__ in_p,
                             const float* __restrict__ in_c)
{
    const int N = 128;
    int b = blockIdx.x, t = threadIdx.x;
    int gi = b*N + t;
    float w  = in_w[gi];
    float px = in_p[gi*2+0], py = in_p[gi*2+1];
    float a  = in_c[gi*4+0], o = in_c[gi*4+1], c = in_c[gi*4+3];

    __shared__ float red[128];
    __shared__ float sval;

    red[t] = 0.5f*(a + c); __syncthreads();
    for (int s = N/2; s > 0; s >>= 1){ if (t < s) red[t] += red[t+s]; __syncthreads(); }
    if (t == 0) sval = rsqrtf(red[0]/(float)N + 1e-8f);
    __syncthreads();
    float f = sval, f2 = f*f;
    px *= f; py *= f; a *= f2; o *= f2; c *= f2;

    float det = a*c - o*o;
    float iv  = fabsf(w)*TWO_PI_F*sqrtf(fmaxf(det, 1e-12f));
    __syncthreads();
    red[t] = iv; __syncthreads();
    for (int s = N/2; s > 0; s >>= 1){ if (t < s) red[t] += red[t+s]; __syncthreads(); }
    if (t == 0) sval = red[0]/(float)N + 1e-6f;
    __syncthreads();
    w /= sval;

    gA(0)[gi]=w;  gA(1)[gi]=px; gA(2)[gi]=py;
    gA(3)[gi]=a;  gA(4)[gi]=o;  gA(5)[gi]=c;
}

// ---------------------------------------------------------------------------
// Fused conv + eval-at-centers, chunked over j, packed f32x2 math.
// ---------------------------------------------------------------------------
template<int Ci, int Nd, int Co, int Nk, int N, int CH, int BLOCK, int IPT>
__global__ void __launch_bounds__(BLOCK) eval_fused_kernel(
    const float* __restrict__ kw, const float* __restrict__ kp,
    const float* __restrict__ kc)
{
    static_assert(N == BLOCK*IPT, "i tiling");
    static_assert(N % CH == 0, "j chunking");
    static_assert(IPT % 2 == 0, "pairing");
    constexpr int NJ = N / CH;
    constexpr int NP = IPT/2;
    int pair  = blockIdx.x / CH;
    int chunk = blockIdx.x - pair*CH;
    int b  = pair / Co;
    int co = pair - b*Co;
    size_t base = (size_t)pair * N;

    __shared__ float4 sJ1[NJ];   // (A, B, C, K)
    __shared__ float4 sJ2[NJ];   // (L1, L2, sgn, 0)

    const float* Aw  = gA(0); const float* Ap0 = gA(1); const float* Ap1 = gA(2);
    const float* Ac00= gA(3); const float* Ac01= gA(4); const float* Ac11= gA(5);

    for (int jj = threadIdx.x; jj < NJ; jj += BLOCK){
        int n  = chunk*NJ + jj;
        int nk = n % Nk;  int t2 = n / Nk;
        int nd = t2 % Nd; int ci = t2 / Nd;
        int di = (b*Ci + ci)*Nd + nd;
        int ki = (co*Ci + ci)*Nk + nk;

        float d00=Ac00[di], d01=Ac01[di], d11=Ac11[di];
        float k00=kc[ki*4+0], k01=kc[ki*4+1], k11=kc[ki*4+3];
        float s00=d00+k00, s01=d01+k01, s11=d11+k11;

        float det_d = d00*d11 - d01*d01;
        float det_k = k00*k11 - k01*k01;
        float det_s = s00*s11 - s01*s01;
        float amp = TWO_PI_F * sqrtf(fmaxf(det_d*det_k/fmaxf(det_s,1e-12f), 1e-20f));
        float wv  = Aw[di]*kw[ki]*amp;
        float px  = Ap0[di] + kp[ki*2+0];
        float py  = Ap1[di] + kp[ki*2+1];
        float inv = 1.0f/det_s;

        float A = -0.5f*s11*inv*L2E_F;
        float Bc =  s01*inv*L2E_F;
        float Cc = -0.5f*s00*inv*L2E_F;
        float l1 = -(2.f*A*px + Bc*py);
        float l2 = -(Bc*px + 2.f*Cc*py);
        float K  = A*px*px + Bc*px*py + Cc*py*py + __log2f(fabsf(wv));
        float sg = copysignf(1.f, wv);

        sJ1[jj] = make_float4(A, Bc, Cc, K);
        sJ2[jj] = make_float4(l1, l2, sg, 0.f);

        gW()  [base+n] = wv;
        gP0() [base+n] = px;  gP1() [base+n] = py;
        gC00()[base+n] = s00; gC01()[base+n] = s01; gC11()[base+n] = s11;
    }
    __syncthreads();

    ull acc2[NP], vx2[NP], vy2[NP], vxx2[NP], vxy2[NP], vyy2[NP];
    #pragma unroll
    for (int p = 0; p < NP; p++){
        float x[2], y[2];
        #pragma unroll
        for (int h = 0; h < 2; h++){
            int i  = threadIdx.x + (2*p+h)*BLOCK;
            int nk = i % Nk;  int t2 = i / Nk;
            int nd = t2 % Nd; int ci = t2 / Nd;
            int di = (b*Ci + ci)*Nd + nd;
            int ki = (co*Ci + ci)*Nk + nk;
            x[h] = Ap0[di] + kp[ki*2+0];
            y[h] = Ap1[di] + kp[ki*2+1];
        }
        vx2 [p] = pk2(x[0],      x[1]);
        vy2 [p] = pk2(y[0],      y[1]);
        vxx2[p] = pk2(x[0]*x[0], x[1]*x[1]);
        vxy2[p] = pk2(x[0]*y[0], x[1]*y[1]);
        vyy2[p] = pk2(y[0]*y[0], y[1]*y[1]);
        acc2[p] = pk2(0.f, 0.f);
    }

    #pragma unroll 2
    for (int jj = 0; jj < NJ; jj++){
        float4 j1 = sJ1[jj];
        float4 j2 = sJ2[jj];
        ull A2  = pk2(j1.x, j1.x), B2  = pk2(j1.y, j1.y);
        ull C2  = pk2(j1.z, j1.z), K2  = pk2(j1.w, j1.w);
        ull L1v = pk2(j2.x, j2.x), L2v = pk2(j2.y, j2.y);
        ull S2  = pk2(j2.z, j2.z);
        #pragma unroll
        for (int p = 0; p < NP; p++){
            ull q = ffma2(L2v, vy2[p], K2);
            q = ffma2(L1v, vx2 [p], q);
            q = ffma2(C2,  vyy2[p], q);
            q = ffma2(B2,  vxy2[p], q);
            q = ffma2(A2,  vxx2[p], q);
            float ql, qh; upk2(ql, qh, q);
            ull e = pk2(ex2f(ql), ex2f(qh));
            acc2[p] = ffma2(S2, e, acc2[p]);
        }
    }

    float* out = gAcc(chunk);
    #pragma unroll
    for (int p = 0; p < NP; p++){
        float a0, a1; upk2(a0, a1, acc2[p]);
        out[base + threadIdx.x + (2*p+0)*BLOCK] = a0;
        out[base + threadIdx.x + (2*p+1)*BLOCK] = a1;
    }
}

// ---------------------------------------------------------------------------
// Fused collapse + top-k select + gather. One 256-thread block per (b,co)
// pair. Phase 1: sum CH partial slots, relu_fit weight update, score -> smem.
// Phase 2 (warp 0): K argmax passes, scores packed u64 = (score<<32)|~idx
// (unsigned max = max score, lowest index on ties = jax.lax.top_k), warp
// reduce via single-instruction redux.sync.max.u32 (score, then tie-broken
// ~index). Phase 3: gather selected components compactly into gA.
// ---------------------------------------------------------------------------
template<int Co, int N, int K, int CH>
__global__ void __launch_bounds__(256) topk_fused_kernel()
{
    constexpr int BLOCK = 256;
    constexpr int R = N/32;
    static_assert(N == R*32, "exact");
    int pair = blockIdx.x;
    size_t ib = (size_t)pair*N, ob = (size_t)pair*K;
    int tid = threadIdx.x;

    __shared__ float    sWn[N];
    __shared__ unsigned sSc[N];
    __shared__ int      sel[K];

    for (int n = tid; n < N; n += BLOCK){
        size_t i = ib + n;
        float s = 0.f;
        #pragma unroll
        for (int c = 0; c < CH; c++) s += gAcc(c)[i];
        float w = gW()[i];
        float denom = (fabsf(s) > 1e-6f) ? s : 1e-6f;
        float wn = w * (fmaxf(s, 0.f)/denom);
        float c00 = gC00()[i], c01 = gC01()[i], c11 = gC11()[i];
        float sq = sqrtf(fmaxf(c00*c11 - c01*c01, 1e-12f));
        sWn[n] = wn;
        sSc[n] = __float_as_uint(fabsf(wn)*sq);
    }
    __syncthreads();

    if (tid < 32){
        int lane = tid;
        ull v[R];
        #pragma unroll
        for (int r = 0; r < R; r++){
            int j = lane + r*32;
            v[r] = ((ull)sSc[j] << 32) | (ull)(unsigned)(~j);
        }
        for (int it = 0; it < K; it++){
            ull m0 = v[0], m1 = v[1], m2 = v[2], m3 = v[3];
            #pragma unroll
            for (int r = 4; r < R; r += 4){
                m0 = umax64(m0, v[r]);
                if (r+1 < R) m1 = umax64(m1, v[r+1]);
                if (r+2 < R) m2 = umax64(m2, v[r+2]);
                if (r+3 < R) m3 = umax64(m3, v[r+3]);
            }
            ull m = umax64(umax64(m0, m1), umax64(m2, m3));
            unsigned smax = redux_max((unsigned)(m >> 32));
            unsigned cand = ((unsigned)(m >> 32) == smax) ? (unsigned)m : 0u;
            unsigned nmax = redux_max(cand);   // ~idx nonzero for idx < 2^31
            ull wv = ((ull)smax << 32) | nmax;
            #pragma unroll
            for (int r = 0; r < R; r++) if (v[r] == wv) v[r] = 0;
            if (lane == 0) sel[it] = (int)(~nmax);
        }
    }
    __syncthreads();

    if (tid < K){
        int idx = sel[tid];
        size_t gi = ib + idx;
        gA(0)[ob+tid] = sWn[idx];
        gA(1)[ob+tid] = gP0() [gi];
        gA(2)[ob+tid] = gP1() [gi];
        gA(3)[ob+tid] = gC00()[gi];
        gA(4)[ob+tid] = gC01()[gi];
        gA(5)[ob+tid] = gC11()[gi];
    }
}

// ---------------------------------------------------------------------------
// Channel-wise CovScaleNorm + WeightBatchNorm over the compact selected set.
// ---------------------------------------------------------------------------
template<int Co, int K>
__global__ void __launch_bounds__(256) chan_norm_kernel()
{
    constexpr int B = 8, BLOCK = 256, M = B*K;
    int co = blockIdx.x, tid = threadIdx.x;
    __shared__ float red[BLOCK];
    __shared__ float sF, sWS;

    size_t oi = 0;
    float tr = 0.f;
    if (tid < M){
        int b = tid / K, t = tid - b*K;
        oi = (size_t)(b*Co + co)*K + t;
        tr = 0.5f*(gA(3)[oi] + gA(5)[oi]);
    }
    red[tid] = tr; __syncthreads();
    for (int s = BLOCK>>1; s; s >>= 1){ if (tid < s) red[tid] += red[tid+s]; __syncthreads(); }
    if (tid == 0) sF = rsqrtf(red[0]/(float)M + 1e-8f);
    __syncthreads();
    float f = sF, f2 = f*f;

    float ab = 0.f;
    if (tid < M){
        float a = gA(3)[oi]*f2, o = gA(4)[oi]*f2, c = gA(5)[oi]*f2;
        float det = a*c - o*o;
        ab = fabsf(gA(0)[oi])*TWO_PI_F*sqrtf(fmaxf(det, 1e-12f));
    }
    red[tid] = ab; __syncthreads();
    for (int s = BLOCK>>1; s; s >>= 1){ if (tid < s) red[tid] += red[tid+s]; __syncthreads(); }
    if (tid == 0) sWS = red[0]/(float)M + 1e-6f;
    __syncthreads();
    float ws = sWS;

    if (tid < M){
        gA(0)[oi] /= ws;
        gA(1)[oi] *= f;  gA(2)[oi] *= f;
        gA(3)[oi] *= f2; gA(4)[oi] *= f2; gA(5)[oi] *= f2;
    }
}

// ---------------------------------------------------------------------------
// Layer2 fused collapse + partials: block per (co,b), sums CH slots ->
// relu_fit -> (tr, u, |u|) partial sums into gY[co][b][3].
// ---------------------------------------------------------------------------
template<int Co, int N, int CH>
__global__ void __launch_bounds__(128) lay2part_kernel()
{
    constexpr int BLOCK = 128;
    int co = blockIdx.x >> 3, b = blockIdx.x & 7;
    int tid = threadIdx.x, lane = tid & 31, wid = tid >> 5;
    size_t base = (size_t)(b*Co + co)*N;

    float tr = 0.f, su = 0.f, sa = 0.f;
    for (int n = tid; n < N; n += BLOCK){
        size_t i = base + n;
        float s = 0.f;
        #pragma unroll
        for (int c = 0; c < CH; c++) s += gAcc(c)[i];
        float w = gW()[i];
        float denom = (fabsf(s) > 1e-6f) ? s : 1e-6f;
        float wn = w * (fmaxf(s, 0.f)/denom);
        float c00 = gC00()[i], c01 = gC01()[i], c11 = gC11()[i];
        float u = wn*TWO_PI_F*sqrtf(fmaxf(c00*c11 - c01*c01, 1e-12f));
        tr += 0.5f*(c00 + c11);
        su += u; sa += fabsf(u);
    }
    #pragma unroll
    for (int off = 16; off; off >>= 1){
        tr += __shfl_down_sync(0xffffffffu, tr, off);
        su += __shfl_down_sync(0xffffffffu, su, off);
        sa += __shfl_down_sync(0xffffffffu, sa, off);
    }
    __shared__ float w3[3][4];
    if (lane == 0){ w3[0][wid] = tr; w3[1][wid] = su; w3[2][wid] = sa; }
    __syncthreads();
    if (tid == 0){
        float* o = gY() + (size_t)(co*8 + b)*3;
        o[0] = w3[0][0]+w3[0][1]+w3[0][2]+w3[0][3];
        o[1] = w3[1][0]+w3[1][1]+w3[1][2]+w3[1][3];
        o[2] = w3[2][0]+w3[2][1]+w3[2][2]+w3[2][3];
    }
}

// ---------------------------------------------------------------------------
// Final: layer2 channel norms + integrate + BatchNorm1d + log_softmax.
// ---------------------------------------------------------------------------
template<int Co, int N>
__global__ void final_kernel(float* __restrict__ out)
{
    constexpr int B = 8;
    __shared__ float sn2[80];
    int t = threadIdx.x;
    if (t < Co){
        int co = t;
        float str = 0.f, ssa = 0.f;
        #pragma unroll
        for (int b = 0; b < B; b++){
            str += gY()[(size_t)(co*8+b)*3 + 0];
            ssa += gY()[(size_t)(co*8+b)*3 + 2];
        }
        float mtr = str/(float)(B*N);
        float fr  = rsqrtf(mtr + 1e-8f);
        float f2  = fr*fr;
        float ws  = f2*ssa/(float)(B*N) + 1e-6f;
        float x[B];
        float mu = 0.f;
        #pragma unroll
        for (int b = 0; b < B; b++){
            x[b] = f2*gY()[(size_t)(co*8+b)*3 + 1]/ws;
            mu += x[b];
        }
        mu *= 0.125f;
        float var = 0.f;
        #pragma unroll
        for (int b = 0; b < B; b++){ float d = x[b]-mu; var += d*d; }
        var *= 0.125f;
        float iv = rsqrtf(var + 1e-5f);
        #pragma unroll
        for (int b = 0; b < B; b++) sn2[b*10+co] = (x[b]-mu)*iv;
    }
    __syncthreads();
    if (t < B){
        float mx = -1e30f;
        for (int c = 0; c < 10; c++) mx = fmaxf(mx, sn2[t*10+c]);
        float se = 0.f;
        for (int c = 0; c < 10; c++) se += expf(sn2[t*10+c] - mx);
        float lse = mx + logf(se);
        for (int c = 0; c < 10; c++) out[t*10+c] = sn2[t*10+c] - lse;
    }
}

// ---------------------------------------------------------------------------
extern "C" void kernel_launch(void* const* d_in, const int* in_sizes, int n_in,
                              void* d_out, int out_size)
{
    const float* in_w = (const float*)d_in[0];
    const float* in_p = (const float*)d_in[1];
    const float* in_c = (const float*)d_in[2];
    const float* k0w  = (const float*)d_in[3];
    const float* k0p  = (const float*)d_in[4];
    const float* k0c  = (const float*)d_in[5];
    const float* k1w  = (const float*)d_in[6];
    const float* k1p  = (const float*)d_in[7];
    const float* k1c  = (const float*)d_in[8];
    const float* k2w  = (const float*)d_in[9];
    const float* k2p  = (const float*)d_in[10];
    const float* k2c  = (const float*)d_in[11];
    float* out = (float*)d_out;

    norm0_kernel<<<8, 128>>>(in_w, in_p, in_c);

    // layer 0: N=640, n_fit=32
    eval_fused_kernel<1,128,8,5, 640,8,64,10><<<64*8, 64>>>(k0w, k0p, k0c);
    topk_fused_kernel<8,640,32,8><<<64, 256>>>();
    chan_norm_kernel<8,32><<<8, 256>>>();

    // layer 1: N=1280, n_fit=16
    eval_fused_kernel<8,32,16,5, 1280,8,128,10><<<128*8, 128>>>(k1w, k1p, k1c);
    topk_fused_kernel<16,1280,16,8><<<128, 256>>>();
    chan_norm_kernel<16,16><<<16, 256>>>();

    // layer 2: N=1280, keep all
    eval_fused_kernel<16,16,10,5, 1280,16,128,10><<<80*16, 128>>>(k2w, k2p, k2c);
    lay2part_kernel<10,1280,16><<<80, 128>>>();
    final_kernel<10,1280><<<1, 128>>>(out);
}